// round 17
// baseline (speedup 1.0000x reference)
#include <cuda_runtime.h>
#include <math.h>
#include <stdint.h>

#define N_   32
#define C_   512
#define HW_  4096          // 64*64
#define D_   4
#define BLK_ 128           // C_/D_
#define HID_ 32            // C_/16
#define CD_  (C_ * D_)     // 2048

// ---- scratch (no allocations allowed) ----
__device__ float g_avgp[N_ * C_];
__device__ float g_maxp[N_ * C_];
__device__ int   g_idx [N_ * C_];   // selected channels, output order
__device__ int   g_cnt [N_];        // per-sample pool-completion counter
                                    // (zero-init at load; self-reset each launch)

// ---------------------------------------------------------------------------
// K1: pooling + (for the last-finishing block of each sample) fused MLP +
// sigmoid + 4-scale top-128 rank. One block per (n,c) row.
//   key = (bits(sigmoid)<<16) | (65535-c): sigmoid>0 -> monotone float bits;
//   low-bits index tiebreak = exact lax.top_k order.
// ---------------------------------------------------------------------------
struct SmemMlp {
    float avg_s[C_], max_s[C_];
    float part_a[8 * HID_], part_m[8 * HID_];
    float hs[HID_];
    __align__(16) unsigned long long keys[D_ * C_];   // [d][c], 16 KB
};
struct SmemPool { float ss[8], sm[8]; };
union SmemU { SmemPool p; SmemMlp m; };

__global__ __launch_bounds__(256) void pool_mlp_kernel(
    const float* __restrict__ x,
    const float* __restrict__ W1, const float* __restrict__ b1,
    const float* __restrict__ W2, const float* __restrict__ b2) {
    __shared__ SmemU sh;
    __shared__ int s_last;
    const int row = blockIdx.x;                      // n*C + c
    const int n   = row >> 9;
    const int tid = threadIdx.x;

    // ---- pool this row ----
    {
        const float4* xr = reinterpret_cast<const float4*>(x + (size_t)row * HW_);
        float s = 0.0f, m = -INFINITY;
        #pragma unroll 4
        for (int i = tid; i < HW_ / 4; i += 256) {
            float4 v = xr[i];
            s += (v.x + v.y) + (v.z + v.w);
            m = fmaxf(m, fmaxf(fmaxf(v.x, v.y), fmaxf(v.z, v.w)));
        }
        #pragma unroll
        for (int off = 16; off > 0; off >>= 1) {
            s += __shfl_xor_sync(0xffffffffu, s, off);
            m = fmaxf(m, __shfl_xor_sync(0xffffffffu, m, off));
        }
        const int wid = tid >> 5, lid = tid & 31;
        if (lid == 0) { sh.p.ss[wid] = s; sh.p.sm[wid] = m; }
        __syncthreads();
        if (tid == 0) {
            float ts = sh.p.ss[0], tm = sh.p.sm[0];
            #pragma unroll
            for (int w = 1; w < 8; w++) { ts += sh.p.ss[w]; tm = fmaxf(tm, sh.p.sm[w]); }
            g_avgp[row] = ts * (1.0f / HW_);
            g_maxp[row] = tm;
            __threadfence();
            s_last = (atomicAdd(&g_cnt[n], 1) == C_ - 1);
        }
        __syncthreads();
    }
    if (!s_last) return;

    // ---- last block of sample n: fused MLP + rank (256 threads) ----
    __threadfence();   // acquire: all 512 pool results for sample n visible
    sh.m.avg_s[tid]       = g_avgp[n * C_ + tid];
    sh.m.avg_s[tid + 256] = g_avgp[n * C_ + tid + 256];
    sh.m.max_s[tid]       = g_maxp[n * C_ + tid];
    sh.m.max_s[tid + 256] = g_maxp[n * C_ + tid + 256];
    __syncthreads();

    // Layer 1 (coalesced): warp w (0..7) handles c = w, w+8, ...; lane = hidden.
    {
        const int w = tid >> 5, j = tid & 31;
        float sa = 0.0f, smx = 0.0f;
        #pragma unroll 8
        for (int c = w; c < C_; c += 8) {
            float w1 = W1[c * HID_ + j];
            sa  = fmaf(sh.m.avg_s[c], w1, sa);
            smx = fmaf(sh.m.max_s[c], w1, smx);
        }
        sh.m.part_a[w * HID_ + j] = sa;
        sh.m.part_m[w * HID_ + j] = smx;
    }
    __syncthreads();
    if (tid < HID_) {
        float sa = 0.0f, smx = 0.0f;
        #pragma unroll
        for (int w = 0; w < 8; w++) {
            sa  += sh.m.part_a[w * HID_ + tid];
            smx += sh.m.part_m[w * HID_ + tid];
        }
        float bb = b1[tid];
        sh.m.hs[tid] = fmaxf(sa + bb, 0.0f) + fmaxf(smx + bb, 0.0f);
    }
    __syncthreads();

    // Layer 2 + sigmoid + keys for ALL 4 scales: 8 outputs per thread,
    // consecutive threads -> consecutive o (fully coalesced W2 rows).
    #pragma unroll
    for (int i = 0; i < 8; i++) {
        const int o = tid + i * 256;
        float acc = 2.0f * b2[o];
        #pragma unroll
        for (int k = 0; k < HID_; k++)
            acc = fmaf(sh.m.hs[k], W2[k * CD_ + o], acc);
        float v = 1.0f / (1.0f + expf(-acc));
        const int c = o >> 2, d = o & 3;
        sh.m.keys[d * C_ + c] =
            ((unsigned long long)__float_as_uint(v) << 16) |
            (unsigned long long)(65535 - c);
    }
    __syncthreads();

    // Rank by count, per scale; thread handles channels tid and tid+256.
    #pragma unroll
    for (int d = 0; d < D_; d++) {
        const unsigned long long k1 = sh.m.keys[d * C_ + tid];
        const unsigned long long k2 = sh.m.keys[d * C_ + tid + 256];
        int r1 = 0, r2 = 0;
        const ulonglong2* kk =
            reinterpret_cast<const ulonglong2*>(&sh.m.keys[d * C_]);
        #pragma unroll 8
        for (int i = 0; i < C_ / 2; i++) {
            ulonglong2 u = kk[i];
            r1 += (u.x > k1) + (u.y > k1);
            r2 += (u.x > k2) + (u.y > k2);
        }
        if (r1 < BLK_) g_idx[n * C_ + d * BLK_ + r1] = tid;
        if (r2 < BLK_) g_idx[n * C_ + d * BLK_ + r2] = tid + 256;
    }
    __syncthreads();
    if (tid == 0) g_cnt[n] = 0;      // self-reset for next graph replay
}

// ---------------------------------------------------------------------------
// K3: gather, REVERSED row order (sample 31 first: just pooled, hottest in
// L2). Front-batched loads (MLP=4), __ldcs last-touch reads, __stcs writes.
// ---------------------------------------------------------------------------
__global__ __launch_bounds__(256) void gather_kernel(
    const float* __restrict__ x, float* __restrict__ out) {
    const int row = (N_ * C_ - 1) - blockIdx.x;      // descending
    const int n   = row >> 9;
    const int c   = g_idx[row];
    const float4* src = reinterpret_cast<const float4*>(
        x + ((size_t)n * C_ + c) * HW_);
    float4* dst = reinterpret_cast<float4*>(out + (size_t)row * HW_);
    const int i = threadIdx.x;
    float4 v0 = __ldcs(src + i);
    float4 v1 = __ldcs(src + i + 256);
    float4 v2 = __ldcs(src + i + 512);
    float4 v3 = __ldcs(src + i + 768);
    __stcs(dst + i,       v0);
    __stcs(dst + i + 256, v1);
    __stcs(dst + i + 512, v2);
    __stcs(dst + i + 768, v3);
}

extern "C" void kernel_launch(void* const* d_in, const int* in_sizes, int n_in,
                              void* d_out, int out_size) {
    const float* x  = (const float*)d_in[0];
    const float* W1 = (const float*)d_in[1];
    const float* b1 = (const float*)d_in[2];
    const float* W2 = (const float*)d_in[3];
    const float* b2 = (const float*)d_in[4];
    float* out = (float*)d_out;

    pool_mlp_kernel<<<N_ * C_, 256>>>(x, W1, b1, W2, b2);
    gather_kernel<<<N_ * C_, 256>>>(x, out);
}